// round 14
// baseline (speedup 1.0000x reference)
#include <cuda_runtime.h>
#include <cuda_fp16.h>
#include <cstdint>
#include <cstddef>

// ---------------- problem constants ----------------
#define T_SEQ 2048
#define DIM   2048
#define NH    16
#define HD    128
#define FFN   8192
#define EPS_F 1.1920929e-07f
#define NEG_INF_F (-1e30f)

// ---------------- scratch (device globals; no runtime allocs) ----------------
__device__ __half g_xn  [(size_t)T_SEQ * DIM];     // fp16 rmsnorm output
__device__ __half g_qkv [(size_t)T_SEQ * 3 * DIM]; // [T, 48, 128] fp16 (QKV GEMM out)
__device__ __half g_qh  [(size_t)T_SEQ * NH * HD]; // fp16 q for flash
__device__ __half g_kh  [(size_t)T_SEQ * NH * HD]; // fp16 shifted k for flash
__device__ __half g_vh  [(size_t)T_SEQ * NH * HD]; // fp16 v for flash
__device__ __half g_y   [(size_t)T_SEQ * DIM];     // fp16 attention output
__device__ float  g_x1  [(size_t)T_SEQ * DIM];
__device__ __half g_h   [(size_t)T_SEQ * FFN];     // fp16 MLP hidden
__device__ float  g_agate[(size_t)T_SEQ * NH];
__device__ float  g_vgate[(size_t)T_SEQ * NH];

// ---------------- helpers ----------------
__device__ __forceinline__ uint32_t pack2h(float a, float b) {
    __half2 h = __floats2half2_rn(a, b);
    return *(uint32_t*)&h;
}
__device__ __forceinline__ void cp_async16(uint32_t dst, const void* src) {
    asm volatile("cp.async.cg.shared.global [%0], [%1], 16;" :: "r"(dst), "l"(src));
}
__device__ __forceinline__ void cp_async_commit() {
    asm volatile("cp.async.commit_group;" ::: "memory");
}
template<int N>
__device__ __forceinline__ void cp_async_wait() {
    asm volatile("cp.async.wait_group %0;" :: "n"(N) : "memory");
}
__device__ __forceinline__ uint32_t smem_u32(const void* p) {
    uint32_t a;
    asm("{ .reg .u64 t; cvta.to.shared.u64 t, %1; cvt.u32.u64 %0, t; }" : "=r"(a) : "l"(p));
    return a;
}
__device__ __forceinline__ void ldsm_x4(uint32_t& r0, uint32_t& r1, uint32_t& r2, uint32_t& r3,
                                        uint32_t addr) {
    asm volatile("ldmatrix.sync.aligned.m8n8.x4.shared.b16 {%0,%1,%2,%3}, [%4];"
                 : "=r"(r0), "=r"(r1), "=r"(r2), "=r"(r3) : "r"(addr));
}
__device__ __forceinline__ void ldsm_x4_t(uint32_t& r0, uint32_t& r1, uint32_t& r2, uint32_t& r3,
                                          uint32_t addr) {
    asm volatile("ldmatrix.sync.aligned.m8n8.x4.trans.shared.b16 {%0,%1,%2,%3}, [%4];"
                 : "=r"(r0), "=r"(r1), "=r"(r2), "=r"(r3) : "r"(addr));
}
__device__ __forceinline__ void mma_f16(float& c0, float& c1, float& c2, float& c3,
                                        uint32_t a0, uint32_t a1, uint32_t a2, uint32_t a3,
                                        uint32_t b0, uint32_t b1) {
    asm volatile("mma.sync.aligned.m16n8k16.row.col.f32.f16.f16.f32 "
                 "{%0,%1,%2,%3}, {%4,%5,%6,%7}, {%8,%9}, {%0,%1,%2,%3};"
                 : "+f"(c0), "+f"(c1), "+f"(c2), "+f"(c3)
                 : "r"(a0), "r"(a1), "r"(a2), "r"(a3), "r"(b0), "r"(b1));
}

// ================= fp16 warp-MMA GEMM with fused fp32->fp16 B conversion =================
// C[M,N] = epi(alpha * A[M,K] @ op(B)); A fp16, B fp32 (converted in-kernel).
// BT=1: B [N,K] row-major. BT=0: B [K,N] row-major.
// BM=256 BN=128 BK=64, 512 threads (16 warps, 4x4 of 64x32 warp tiles).
// A: 4-stage cp.async; B: LDG fp32 -> regs -> convert -> STS fp16, 2-stage ring.
#define GBM 256
#define GBN 128
#define GBK 64
#define GSTAGES 4
#define ROWH 72
#define BROWB 272
#define A_STAGE_B (GBM * ROWH * 2)            // 36864 bytes
#define B_STAGE_B 18432
#define B_BASE (GSTAGES * A_STAGE_B)          // 147456
#define GEMM_SMEM (B_BASE + 2 * B_STAGE_B)    // 184320 bytes

// EPI: 0=none->half, 1=relu^2->half, 2=add residual->float
template<int EPI, int BT>
__global__ void __launch_bounds__(512, 1)
f16_gemm_kernel(const __half* __restrict__ A, const float* __restrict__ B,
                void* __restrict__ Cv, const float* __restrict__ addsrc,
                const float* __restrict__ alpha_ptr, int alpha_idx,
                int N, int K)
{
    extern __shared__ char smc[];
    const int tid = threadIdx.x;
    const int wid = tid >> 5, lane = tid & 31;
    const int g = lane >> 2, tig = lane & 3;
    const int wm = (wid & 3) * 64, wn = (wid >> 2) * 32;
    const int bn = blockIdx.x, bm = blockIdx.y;
    const int nk = K / GBK;
    const uint32_t sb = smem_u32(smc);

    const __half* Agm = A + (size_t)bm * GBM * K;
    const float*  Bgm = BT ? (B + (size_t)bn * GBN * K) : B;

    auto load_A = [&](int stage, int ktile) {
        uint32_t sa = sb + stage * A_STAGE_B;
        int kt = ktile * GBK;
        #pragma unroll
        for (int i = 0; i < 4; i++) {
            int c = tid + i * 512;
            int row = c >> 3, ch = c & 7;
            cp_async16(sa + (uint32_t)row * 144 + ch * 16,
                       Agm + (size_t)row * K + kt + ch * 8);
        }
    };

    float4 breg[2][2];
    auto ldg_B = [&](int ktile) {
        int kt = ktile * GBK;
        #pragma unroll
        for (int i = 0; i < 2; i++) {
            int c = tid + i * 512;
            const float* p;
            if (BT) {
                int row = c >> 3, ch = c & 7;
                p = Bgm + (size_t)row * K + kt + ch * 8;
            } else {
                int row = c >> 4, ch = c & 15;
                p = Bgm + (size_t)(kt + row) * N + bn * GBN + ch * 8;
            }
            breg[i][0] = *(const float4*)p;
            breg[i][1] = *(const float4*)(p + 4);
        }
    };
    auto sts_B = [&](int bstage) {
        #pragma unroll
        for (int i = 0; i < 2; i++) {
            int c = tid + i * 512;
            uint32_t off;
            if (BT) { int row = c >> 3, ch = c & 7;  off = (uint32_t)row * 144 + ch * 16; }
            else    { int row = c >> 4, ch = c & 15; off = (uint32_t)row * BROWB + ch * 16; }
            uint4 o;
            o.x = pack2h(breg[i][0].x, breg[i][0].y);
            o.y = pack2h(breg[i][0].z, breg[i][0].w);
            o.z = pack2h(breg[i][1].x, breg[i][1].y);
            o.w = pack2h(breg[i][1].z, breg[i][1].w);
            *(uint4*)&smc[B_BASE + bstage * B_STAGE_B + off] = o;
        }
    };

    uint32_t aoff[4], boff[2];
    #pragma unroll
    for (int mt = 0; mt < 4; mt++)
        aoff[mt] = (uint32_t)(wm + mt * 16 + (lane & 7) + ((lane >> 3) & 1) * 8) * 144
                 + ((lane >> 4) & 1) * 16;
    if (BT) {
        #pragma unroll
        for (int nb = 0; nb < 2; nb++)
            boff[nb] = (uint32_t)(wn + nb * 16 + (lane & 7) + ((lane >> 4) & 1) * 8) * 144
                     + ((lane >> 3) & 1) * 16;
    } else {
        #pragma unroll
        for (int nb = 0; nb < 2; nb++)
            boff[nb] = (uint32_t)((lane & 7) + ((lane >> 3) & 1) * 8) * BROWB
                     + (wn + nb * 16) * 2 + ((lane >> 4) & 1) * 16;
    }

    float acc[4][4][4];
    #pragma unroll
    for (int mt = 0; mt < 4; mt++)
        #pragma unroll
        for (int nt = 0; nt < 4; nt++)
            #pragma unroll
            for (int q = 0; q < 4; q++) acc[mt][nt][q] = 0.f;

    ldg_B(0); sts_B(0);
    ldg_B(1);
    #pragma unroll
    for (int s = 0; s < GSTAGES - 1; s++) { load_A(s, s); cp_async_commit(); }

    for (int k = 0; k < nk; k++) {
        cp_async_wait<GSTAGES - 2>();
        __syncthreads();
        if (k + 1 < nk) sts_B((k + 1) & 1);
        if (k + 2 < nk) ldg_B(k + 2);
        if (k + GSTAGES - 1 < nk) load_A((k + GSTAGES - 1) & (GSTAGES - 1),
                                         k + GSTAGES - 1);
        cp_async_commit();

        uint32_t sa = sb + (k & (GSTAGES - 1)) * A_STAGE_B;
        uint32_t sB = sb + B_BASE + (k & 1) * B_STAGE_B;

        #pragma unroll
        for (int ks = 0; ks < 4; ks++) {
            uint32_t a[4][4];
            #pragma unroll
            for (int mt = 0; mt < 4; mt++)
                ldsm_x4(a[mt][0], a[mt][1], a[mt][2], a[mt][3],
                        sa + aoff[mt] + ks * 32);
            #pragma unroll
            for (int nb = 0; nb < 2; nb++) {
                uint32_t b0, b1, b2, b3;
                if (BT) ldsm_x4(b0, b1, b2, b3, sB + boff[nb] + ks * 32);
                else    ldsm_x4_t(b0, b1, b2, b3, sB + boff[nb] + ks * 16 * BROWB);
                #pragma unroll
                for (int mt = 0; mt < 4; mt++) {
                    mma_f16(acc[mt][2 * nb][0], acc[mt][2 * nb][1],
                            acc[mt][2 * nb][2], acc[mt][2 * nb][3],
                            a[mt][0], a[mt][1], a[mt][2], a[mt][3], b0, b1);
                    mma_f16(acc[mt][2 * nb + 1][0], acc[mt][2 * nb + 1][1],
                            acc[mt][2 * nb + 1][2], acc[mt][2 * nb + 1][3],
                            a[mt][0], a[mt][1], a[mt][2], a[mt][3], b2, b3);
                }
            }
        }
    }

    float alpha = alpha_ptr ? alpha_ptr[alpha_idx] : 1.0f;
    #pragma unroll
    for (int mt = 0; mt < 4; mt++) {
        #pragma unroll
        for (int half_i = 0; half_i < 2; half_i++) {
            int row = bm * GBM + wm + mt * 16 + g + half_i * 8;
            #pragma unroll
            for (int nt = 0; nt < 4; nt++) {
                int col = bn * GBN + wn + nt * 8 + tig * 2;
                float vx = acc[mt][nt][half_i * 2 + 0] * alpha;
                float vy = acc[mt][nt][half_i * 2 + 1] * alpha;
                size_t idx = (size_t)row * N + col;
                if (EPI == 1) {
                    vx = fmaxf(vx, 0.f); vx = vx * vx;
                    vy = fmaxf(vy, 0.f); vy = vy * vy;
                    *(__half2*)((__half*)Cv + idx) = __floats2half2_rn(vx, vy);
                } else if (EPI == 2) {
                    float2 a2 = *(const float2*)&addsrc[idx];
                    float2 v; v.x = vx + a2.x; v.y = vy + a2.y;
                    *(float2*)((float*)Cv + idx) = v;
                } else {
                    *(__half2*)((__half*)Cv + idx) = __floats2half2_rn(vx, vy);
                }
            }
        }
    }
}

// ---------------- RMSNorm (fp16 output) ----------------
__global__ void __launch_bounds__(256) rmsnorm_kernel(const float* __restrict__ in,
                                                      __half* __restrict__ outp) {
    int t = blockIdx.x;
    const float* r = in + (size_t)t * DIM;
    float ss = 0.f;
    float vals[8];
    #pragma unroll
    for (int j = 0; j < 8; j++) {
        float v = r[threadIdx.x + j * 256];
        vals[j] = v; ss += v * v;
    }
    __shared__ float sred[8];
    for (int o = 16; o; o >>= 1) ss += __shfl_xor_sync(0xffffffffu, ss, o);
    if ((threadIdx.x & 31) == 0) sred[threadIdx.x >> 5] = ss;
    __syncthreads();
    float tot = 0.f;
    #pragma unroll
    for (int i = 0; i < 8; i++) tot += sred[i];
    float scale = rsqrtf(tot / (float)DIM + EPS_F);
    #pragma unroll
    for (int j = 0; j < 8; j++)
        outp[(size_t)t * DIM + threadIdx.x + j * 256] = __float2half_rn(vals[j] * scale);
}

// ---------------- gates v2: tiled, low weight traffic ----------------
__global__ void __launch_bounds__(256) gates2_kernel(
    const __half* __restrict__ xn, const float* __restrict__ agw,
    const float* __restrict__ vgw, float* __restrict__ agate,
    float* __restrict__ vgate)
{
    __shared__ __half xs[16][520];
    int t0 = blockIdx.x * 16;
    int t = threadIdx.x & 15, og = threadIdx.x >> 4;
    float acc0 = 0.f, acc1 = 0.f;
    for (int kc = 0; kc < 4; kc++) {
        #pragma unroll
        for (int i = 0; i < 4; i++) {
            int c = threadIdx.x + i * 256;
            int r = c >> 6, co = c & 63;
            *(uint4*)&xs[r][co * 8] =
                *(const uint4*)&xn[(size_t)(t0 + r) * DIM + kc * 512 + co * 8];
        }
        __syncthreads();
        const float* wa = agw + (size_t)og * DIM + kc * 512;
        const float* wv = vgw + (size_t)og * DIM + kc * 512;
        #pragma unroll 8
        for (int kk = 0; kk < 512; kk++) {
            float xv = __half2float(xs[t][kk]);
            acc0 = fmaf(xv, wa[kk], acc0);
            acc1 = fmaf(xv, wv[kk], acc1);
        }
        __syncthreads();
    }
    agate[(t0 + t) * NH + og] = 1.f / (1.f + expf(-acc0));
    vgate[(t0 + t) * NH + og] = 1.f / (1.f + expf(-acc1));
}

// ---------------- fused QKV post-processing (qkv is fp16 now) ----------------
// slot 0..15: q rmsnorm+rotary -> qh; 16..31: k rmsnorm+rotary -> scatter kh;
// 32..47: v + vgate*ve -> vh
__global__ void __launch_bounds__(256) qkvpost_kernel(
    const __half* __restrict__ qkv, __half* __restrict__ qh,
    __half* __restrict__ kh, __half* __restrict__ vh,
    const float* __restrict__ ve, const float* __restrict__ vgate,
    const float* __restrict__ cosb, const float* __restrict__ sinb,
    const int* __restrict__ key_offset)
{
    int gw = blockIdx.x * 8 + (threadIdx.x >> 5);
    int lane = threadIdx.x & 31;
    int hs = gw % 48;
    int t  = gw / 48;
    int d0 = lane * 4;

    uint2 rv = *(const uint2*)&qkv[((size_t)t * 48 + hs) * HD + d0];
    __half2 h0 = *(__half2*)&rv.x, h1 = *(__half2*)&rv.y;
    float4 v;
    v.x = __low2float(h0); v.y = __high2float(h0);
    v.z = __low2float(h1); v.w = __high2float(h1);

    if (hs >= 32) {
        int h = hs - 32;
        float4 e = *(const float4*)&ve[((size_t)t * NH + h) * HD + d0];
        float gv = vgate[t * NH + h];
        uint2 hv;
        hv.x = pack2h(v.x + gv * e.x, v.y + gv * e.y);
        hv.y = pack2h(v.z + gv * e.z, v.w + gv * e.w);
        *(uint2*)&vh[((size_t)t * NH + h) * HD + d0] = hv;
        return;
    }

    float ss = v.x * v.x + v.y * v.y + v.z * v.z + v.w * v.w;
    #pragma unroll
    for (int o = 16; o; o >>= 1) ss += __shfl_xor_sync(0xffffffffu, ss, o);
    float sc = rsqrtf(ss / (float)HD + EPS_F);
    v.x *= sc; v.y *= sc; v.z *= sc; v.w *= sc;

    float px = __shfl_xor_sync(0xffffffffu, v.x, 16);
    float py = __shfl_xor_sync(0xffffffffu, v.y, 16);
    float pz = __shfl_xor_sync(0xffffffffu, v.z, 16);
    float pw = __shfl_xor_sync(0xffffffffu, v.w, 16);

    int ci = t * 64 + (d0 & 63);
    float4 c = *(const float4*)&cosb[ci];
    float4 s = *(const float4*)&sinb[ci];
    float4 o4;
    if (lane < 16) {
        o4.x = v.x * c.x + px * s.x;
        o4.y = v.y * c.y + py * s.y;
        o4.z = v.z * c.z + pz * s.z;
        o4.w = v.w * c.w + pw * s.w;
    } else {
        o4.x = -px * s.x + v.x * c.x;
        o4.y = -py * s.y + v.y * c.y;
        o4.z = -pz * s.z + v.z * c.z;
        o4.w = -pw * s.w + v.w * c.w;
    }
    uint2 hv;
    hv.x = pack2h(o4.x, o4.y);
    hv.y = pack2h(o4.z, o4.w);

    if (hs < 16) {
        *(uint2*)&qh[((size_t)t * NH + hs) * HD + d0] = hv;
    } else {
        int h = hs - 16;
        int ko = key_offset[0];
        bool up = ((d0 >> 5) & 1) != 0;   // quarters 1 and 3
        if (!ko || !up) {
            *(uint2*)&kh[((size_t)t * NH + h) * HD + d0] = hv;
        } else {
            if (t + 1 < T_SEQ)
                *(uint2*)&kh[((size_t)(t + 1) * NH + h) * HD + d0] = hv;
            if (t == 0)
                *(uint2*)&kh[((size_t)0 * NH + h) * HD + d0] = hv;
        }
    }
}

// ================= fp16 MMA flash attention (double-buffered K/V via cp.async) ======
#define FROW 136
#define KV_STAGE_H (2 * 64 * FROW)               // halfs per stage (K then V)
#define FL_SMEM ((64 * FROW + 2 * KV_STAGE_H) * 2 + 512)

__global__ void __launch_bounds__(128) flash_mma_kernel(
    const __half* __restrict__ qh, const __half* __restrict__ kh,
    const __half* __restrict__ vh, const int* __restrict__ docs,
    const float* __restrict__ attn_scale, const float* __restrict__ agate,
    __half* __restrict__ y)
{
    extern __shared__ __half fh[];
    __half* Qs = fh;                                  // 64 x FROW
    __half* KV0 = fh + 64 * FROW;                     // stage0: K(64xFROW), V(64xFROW)
    __half* KV1 = KV0 + KV_STAGE_H;                   // stage1
    int*    kd  = (int*)(KV1 + KV_STAGE_H);           // [2][64]

    const int tid = threadIdx.x, wid = tid >> 5, lane = tid & 31;
    const int g = lane >> 2, tig = lane & 3;
    const int h = blockIdx.y;
    const int qi = (int)gridDim.x - 1 - (int)blockIdx.x;
    const int qbase = qi * 64;
    const float scale = attn_scale[0];

    #pragma unroll
    for (int i = 0; i < 8; i++) {
        int c = tid + i * 128;
        int r = c >> 4, co = c & 15;
        *(uint4*)&Qs[r * FROW + co * 8] =
            *(const uint4*)&qh[((size_t)(qbase + r) * NH + h) * HD + co * 8];
    }
    const int rg0 = qbase + wid * 16 + g;
    const int rg1 = rg0 + 8;
    const int qd0 = docs[rg0], qd1 = docs[rg1];
    const int qdmin = docs[qbase];

    const uint32_t sQ = smem_u32(Qs);
    const uint32_t sKV[2] = { smem_u32(KV0), smem_u32(KV1) };
    const uint32_t qoff = (uint32_t)(wid * 16 + (lane & 7) + ((lane >> 3) & 1) * 8) * (FROW * 2)
                        + ((lane >> 4) & 1) * 16;
    uint32_t koff[4], voff[8];
    #pragma unroll
    for (int nb = 0; nb < 4; nb++)
        koff[nb] = (uint32_t)(nb * 16 + (lane & 7) + ((lane >> 4) & 1) * 8) * (FROW * 2)
                 + ((lane >> 3) & 1) * 16;
    #pragma unroll
    for (int nb = 0; nb < 8; nb++)
        voff[nb] = (uint32_t)(64 + (lane & 7) + ((lane >> 3) & 1) * 8) * (FROW * 2)
                 + nb * 32 + ((lane >> 4) & 1) * 16;

    // cp.async loader for KV tile kb into stage st (K rows then V rows) + kd
    auto load_kv = [&](int kb, int st) {
        int kbase = kb * 64;
        uint32_t base = sKV[st];
        #pragma unroll
        for (int i = 0; i < 4; i++) {                 // K: 512 chunks of 16B
            int c = tid + i * 128;
            int r = c >> 2, co = (c & 3) * 16;        // 4 chunks per row (128 halfs = 4x16B... )
            // 64 rows x 128 halfs = 64 x 16 chunks of 8 halfs; redo: 1024 chunks of 16B? 
            // 128 halfs * 2B = 256B = 16 chunks of 16B per row; 64 rows -> 1024 chunks; 128 thr x 8
            (void)r; (void)co;
        }
        #pragma unroll
        for (int i = 0; i < 8; i++) {
            int c = tid + i * 128;                    // 0..1023
            int r = c >> 4, co = c & 15;
            cp_async16(base + ((uint32_t)r * FROW + co * 8) * 2,
                       &kh[((size_t)(kbase + r) * NH + h) * HD + co * 8]);
        }
        #pragma unroll
        for (int i = 0; i < 8; i++) {
            int c = tid + i * 128;
            int r = c >> 4, co = c & 15;
            cp_async16(base + ((uint32_t)(64 + r) * FROW + co * 8) * 2,
                       &vh[((size_t)(kbase + r) * NH + h) * HD + co * 8]);
        }
        if (tid < 16)
            cp_async16(smem_u32(&kd[st * 64 + tid * 4]), &docs[kbase + tid * 4]);
    };
    auto next_valid = [&](int kb) {
        int n = kb + 1;
        while (n <= qi && docs[n * 64 + 63] < qdmin) n++;
        return n;
    };

    float o[16][4] = {};
    float m0 = NEG_INF_F, m1 = NEG_INF_F, l0 = 0.f, l1 = 0.f;

    int kb0 = 0;
    while (kb0 <= qi && docs[kb0 * 64 + 63] < qdmin) kb0++;
    load_kv(kb0, 0);
    cp_async_commit();

    int kb = kb0, st = 0;
    __syncthreads();   // Q tile + kd visibility

    while (kb <= qi) {
        int kn = next_valid(kb);
        if (kn <= qi) { load_kv(kn, st ^ 1); cp_async_commit(); cp_async_wait<1>(); }
        else          { cp_async_wait<0>(); }
        __syncthreads();

        const uint32_t sb = sKV[st];
        const int* kdl = &kd[st * 64];
        const int kbase = kb * 64;

        float s[8][4] = {};
        #pragma unroll
        for (int ks = 0; ks < 8; ks++) {
            uint32_t a0, a1, a2, a3;
            ldsm_x4(a0, a1, a2, a3, sQ + qoff + ks * 32);
            #pragma unroll
            for (int nb = 0; nb < 4; nb++) {
                uint32_t b0, b1, b2, b3;
                ldsm_x4(b0, b1, b2, b3, sb + koff[nb] + ks * 32);
                mma_f16(s[2 * nb][0], s[2 * nb][1], s[2 * nb][2], s[2 * nb][3],
                        a0, a1, a2, a3, b0, b1);
                mma_f16(s[2 * nb + 1][0], s[2 * nb + 1][1], s[2 * nb + 1][2], s[2 * nb + 1][3],
                        a0, a1, a2, a3, b2, b3);
            }
        }

        float mx0 = m0, mx1 = m1;
        #pragma unroll
        for (int nt = 0; nt < 8; nt++) {
            int c0i = kbase + nt * 8 + 2 * tig;
            int d0 = kdl[nt * 8 + 2 * tig], d1 = kdl[nt * 8 + 2 * tig + 1];
            float v00 = (c0i     <= rg0 && d0 == qd0) ? s[nt][0] * scale : NEG_INF_F;
            float v01 = (c0i + 1 <= rg0 && d1 == qd0) ? s[nt][1] * scale : NEG_INF_F;
            float v10 = (c0i     <= rg1 && d0 == qd1) ? s[nt][2] * scale : NEG_INF_F;
            float v11 = (c0i + 1 <= rg1 && d1 == qd1) ? s[nt][3] * scale : NEG_INF_F;
            s[nt][0] = v00; s[nt][1] = v01; s[nt][2] = v10; s[nt][3] = v11;
            mx0 = fmaxf(mx0, fmaxf(v00, v01));
            mx1 = fmaxf(mx1, fmaxf(v10, v11));
        }
        mx0 = fmaxf(mx0, __shfl_xor_sync(0xffffffffu, mx0, 1));
        mx0 = fmaxf(mx0, __shfl_xor_sync(0xffffffffu, mx0, 2));
        mx1 = fmaxf(mx1, __shfl_xor_sync(0xffffffffu, mx1, 1));
        mx1 = fmaxf(mx1, __shfl_xor_sync(0xffffffffu, mx1, 2));
        float al0 = __expf(m0 - mx0), al1 = __expf(m1 - mx1);
        m0 = mx0; m1 = mx1;

        float sum0 = 0.f, sum1 = 0.f;
        #pragma unroll
        for (int nt = 0; nt < 8; nt++) {
            s[nt][0] = __expf(s[nt][0] - m0);
            s[nt][1] = __expf(s[nt][1] - m0);
            s[nt][2] = __expf(s[nt][2] - m1);
            s[nt][3] = __expf(s[nt][3] - m1);
            sum0 += s[nt][0] + s[nt][1];
            sum1 += s[nt][2] + s[nt][3];
        }
        sum0 += __shfl_xor_sync(0xffffffffu, sum0, 1);
        sum0 += __shfl_xor_sync(0xffffffffu, sum0, 2);
        sum1 += __shfl_xor_sync(0xffffffffu, sum1, 1);
        sum1 += __shfl_xor_sync(0xffffffffu, sum1, 2);
        l0 = l0 * al0 + sum0;
        l1 = l1 * al1 + sum1;
        #pragma unroll
        for (int nt = 0; nt < 16; nt++) {
            o[nt][0] *= al0; o[nt][1] *= al0;
            o[nt][2] *= al1; o[nt][3] *= al1;
        }

        uint32_t pa[4][4];
        #pragma unroll
        for (int kc = 0; kc < 4; kc++) {
            pa[kc][0] = pack2h(s[2 * kc][0], s[2 * kc][1]);
            pa[kc][1] = pack2h(s[2 * kc][2], s[2 * kc][3]);
            pa[kc][2] = pack2h(s[2 * kc + 1][0], s[2 * kc + 1][1]);
            pa[kc][3] = pack2h(s[2 * kc + 1][2], s[2 * kc + 1][3]);
        }
        #pragma unroll
        for (int kc = 0; kc < 4; kc++) {
            #pragma unroll
            for (int nb = 0; nb < 8; nb++) {
                uint32_t b0, b1, b2, b3;
                ldsm_x4_t(b0, b1, b2, b3, sb + voff[nb] + kc * 16 * (FROW * 2));
                mma_f16(o[2 * nb][0], o[2 * nb][1], o[2 * nb][2], o[2 * nb][3],
                        pa[kc][0], pa[kc][1], pa[kc][2], pa[kc][3], b0, b1);
                mma_f16(o[2 * nb + 1][0], o[2 * nb + 1][1], o[2 * nb + 1][2], o[2 * nb + 1][3],
                        pa[kc][0], pa[kc][1], pa[kc][2], pa[kc][3], b2, b3);
            }
        }
        __syncthreads();   // stage st free for the tile after next
        kb = kn; st ^= 1;
    }

    float f0 = (1.f / l0) * agate[rg0 * NH + h];
    float f1 = (1.f / l1) * agate[rg1 * NH + h];
    #pragma unroll
    for (int nt = 0; nt < 16; nt++) {
        *(__half2*)&y[(size_t)rg0 * DIM + h * HD + nt * 8 + 2 * tig] =
            __floats2half2_rn(o[nt][0] * f0, o[nt][1] * f0);
        *(__half2*)&y[(size_t)rg1 * DIM + h * HD + nt * 8 + 2 * tig] =
            __floats2half2_rn(o[nt][2] * f1, o[nt][3] * f1);
    }
}

// ---------------- launch ----------------
extern "C" void kernel_launch(void* const* d_in, const int* in_sizes, int n_in,
                              void* d_out, int out_size) {
    const float* x           = (const float*)d_in[0];
    const float* ve          = (const float*)d_in[1];
    const float* qkvo_w      = (const float*)d_in[2];
    const float* attn_gate_w = (const float*)d_in[3];
    const float* ve_gate_w   = (const float*)d_in[4];
    const float* c_fc        = (const float*)d_in[5];
    const float* c_proj      = (const float*)d_in[6];
    const float* sa_lambdas  = (const float*)d_in[7];
    const float* cosb        = (const float*)d_in[8];
    const float* sinb        = (const float*)d_in[9];
    const float* attn_scale  = (const float*)d_in[10];
    const int*   docs        = (const int*)d_in[11];
    const int*   key_offset  = (const int*)d_in[12];
    float*       out         = (float*)d_out;

    __half *xn, *qkv, *qhp, *khp, *vhp, *y, *hbuf;
    float *x1, *agate, *vgate;
    cudaGetSymbolAddress((void**)&xn,    g_xn);
    cudaGetSymbolAddress((void**)&qkv,   g_qkv);
    cudaGetSymbolAddress((void**)&qhp,   g_qh);
    cudaGetSymbolAddress((void**)&khp,   g_kh);
    cudaGetSymbolAddress((void**)&vhp,   g_vh);
    cudaGetSymbolAddress((void**)&y,     g_y);
    cudaGetSymbolAddress((void**)&x1,    g_x1);
    cudaGetSymbolAddress((void**)&hbuf,  g_h);
    cudaGetSymbolAddress((void**)&agate, g_agate);
    cudaGetSymbolAddress((void**)&vgate, g_vgate);

    cudaFuncSetAttribute(flash_mma_kernel, cudaFuncAttributeMaxDynamicSharedMemorySize,
                         FL_SMEM);
    cudaFuncSetAttribute((const void*)f16_gemm_kernel<0,1>,
                         cudaFuncAttributeMaxDynamicSharedMemorySize, GEMM_SMEM);
    cudaFuncSetAttribute((const void*)f16_gemm_kernel<1,1>,
                         cudaFuncAttributeMaxDynamicSharedMemorySize, GEMM_SMEM);
    cudaFuncSetAttribute((const void*)f16_gemm_kernel<2,1>,
                         cudaFuncAttributeMaxDynamicSharedMemorySize, GEMM_SMEM);
    cudaFuncSetAttribute((const void*)f16_gemm_kernel<2,0>,
                         cudaFuncAttributeMaxDynamicSharedMemorySize, GEMM_SMEM);

    // 1. xn = fp16(rmsnorm(x))
    rmsnorm_kernel<<<T_SEQ, 256>>>(x, xn);
    // 2. gate logits
    gates2_kernel<<<T_SEQ / 16, 256>>>(xn, attn_gate_w, ve_gate_w, agate, vgate);
    // 3. qkv = fp16(lam0 * xn @ Wqkv^T)
    f16_gemm_kernel<0,1><<<dim3(3 * DIM / GBN, T_SEQ / GBM), 512, GEMM_SMEM>>>(
        xn, qkvo_w, qkv, nullptr, sa_lambdas, 0, 3 * DIM, DIM);
    // 4. fused QKV post (q/k rmsnorm+rotary with scatter shift, v update)
    qkvpost_kernel<<<(T_SEQ * 48) / 8, 256>>>(
        qkv, qhp, khp, vhp, ve, vgate, cosb, sinb, key_offset);
    // 5. fp16 MMA flash attention (double-buffered K/V) -> y (fp16)
    flash_mma_kernel<<<dim3(T_SEQ / 64, NH), 128, FL_SMEM>>>(
        qhp, khp, vhp, docs, attn_scale, agate, y);
    // 6. x1 = x + lam1 * y @ Wo^T
    f16_gemm_kernel<2,1><<<dim3(DIM / GBN, T_SEQ / GBM), 512, GEMM_SMEM>>>(
        y, qkvo_w + (size_t)3 * DIM * DIM, x1, x, sa_lambdas, 1, DIM, DIM);
    // 7. xn = fp16(rmsnorm(x1))
    rmsnorm_kernel<<<T_SEQ, 256>>>(x1, xn);
    // 8. h = fp16(relu(xn @ c_fc^T)^2)
    f16_gemm_kernel<1,1><<<dim3(FFN / GBN, T_SEQ / GBM), 512, GEMM_SMEM>>>(
        xn, c_fc, hbuf, nullptr, nullptr, 0, FFN, DIM);
    // 9. out = x1 + h @ c_proj  (B native [K,N] fp32, trans-ldmatrix path)
    f16_gemm_kernel<2,0><<<dim3(DIM / GBN, T_SEQ / GBM), 512, GEMM_SMEM>>>(
        hbuf, c_proj, out, x1, nullptr, 0, DIM, FFN);
}

// round 15
// speedup vs baseline: 1.0056x; 1.0056x over previous
#include <cuda_runtime.h>
#include <cuda_fp16.h>
#include <cstdint>
#include <cstddef>

// ---------------- problem constants ----------------
#define T_SEQ 2048
#define DIM   2048
#define NH    16
#define HD    128
#define FFN   8192
#define EPS_F 1.1920929e-07f
#define NEG_INF_F (-1e30f)

// ---------------- scratch (device globals; no runtime allocs) ----------------
__device__ __half g_xn  [(size_t)T_SEQ * DIM];     // fp16 rmsnorm output
__device__ float  g_qkv [(size_t)T_SEQ * 3 * DIM]; // [T, 48, 128] fp32
__device__ __half g_qh  [(size_t)T_SEQ * NH * HD]; // fp16 q for flash
__device__ __half g_kh  [(size_t)T_SEQ * NH * HD]; // fp16 shifted k for flash
__device__ __half g_vh  [(size_t)T_SEQ * NH * HD]; // fp16 v for flash
__device__ __half g_y   [(size_t)T_SEQ * DIM];     // fp16 attention output
__device__ float  g_x1  [(size_t)T_SEQ * DIM];
__device__ __half g_h   [(size_t)T_SEQ * FFN];     // fp16 MLP hidden
__device__ float  g_agate[(size_t)T_SEQ * NH];
__device__ float  g_vgate[(size_t)T_SEQ * NH];

// ---------------- helpers ----------------
__device__ __forceinline__ uint32_t pack2h(float a, float b) {
    __half2 h = __floats2half2_rn(a, b);
    return *(uint32_t*)&h;
}
__device__ __forceinline__ void cp_async16(uint32_t dst, const void* src) {
    asm volatile("cp.async.cg.shared.global [%0], [%1], 16;" :: "r"(dst), "l"(src));
}
__device__ __forceinline__ void cp_async_commit() {
    asm volatile("cp.async.commit_group;" ::: "memory");
}
template<int N>
__device__ __forceinline__ void cp_async_wait() {
    asm volatile("cp.async.wait_group %0;" :: "n"(N) : "memory");
}
__device__ __forceinline__ uint32_t smem_u32(const void* p) {
    uint32_t a;
    asm("{ .reg .u64 t; cvta.to.shared.u64 t, %1; cvt.u32.u64 %0, t; }" : "=r"(a) : "l"(p));
    return a;
}
__device__ __forceinline__ void ldsm_x4(uint32_t& r0, uint32_t& r1, uint32_t& r2, uint32_t& r3,
                                        uint32_t addr) {
    asm volatile("ldmatrix.sync.aligned.m8n8.x4.shared.b16 {%0,%1,%2,%3}, [%4];"
                 : "=r"(r0), "=r"(r1), "=r"(r2), "=r"(r3) : "r"(addr));
}
__device__ __forceinline__ void ldsm_x4_t(uint32_t& r0, uint32_t& r1, uint32_t& r2, uint32_t& r3,
                                          uint32_t addr) {
    asm volatile("ldmatrix.sync.aligned.m8n8.x4.trans.shared.b16 {%0,%1,%2,%3}, [%4];"
                 : "=r"(r0), "=r"(r1), "=r"(r2), "=r"(r3) : "r"(addr));
}
__device__ __forceinline__ void mma_f16(float& c0, float& c1, float& c2, float& c3,
                                        uint32_t a0, uint32_t a1, uint32_t a2, uint32_t a3,
                                        uint32_t b0, uint32_t b1) {
    asm volatile("mma.sync.aligned.m16n8k16.row.col.f32.f16.f16.f32 "
                 "{%0,%1,%2,%3}, {%4,%5,%6,%7}, {%8,%9}, {%0,%1,%2,%3};"
                 : "+f"(c0), "+f"(c1), "+f"(c2), "+f"(c3)
                 : "r"(a0), "r"(a1), "r"(a2), "r"(a3), "r"(b0), "r"(b1));
}

// ================= fp16 warp-MMA GEMM with fused fp32->fp16 B conversion =================
// C[M,N] = epi(alpha * A[M,K] @ op(B)); A fp16, B fp32 (converted in-kernel).
// BT=1: B [N,K] row-major. BT=0: B [K,N] row-major.
// BM=256 BN=128 BK=64, 512 threads (16 warps, 4x4 of 64x32 warp tiles).
// A: 4-stage cp.async; B: LDG fp32 -> regs -> convert -> STS fp16, 2-stage ring.
#define GBM 256
#define GBN 128
#define GBK 64
#define GSTAGES 4
#define ROWH 72
#define BROWB 272
#define A_STAGE_B (GBM * ROWH * 2)            // 36864 bytes
#define B_STAGE_B 18432
#define B_BASE (GSTAGES * A_STAGE_B)          // 147456
#define GEMM_SMEM (B_BASE + 2 * B_STAGE_B)    // 184320 bytes

// EPI: 0=none->float, 1=relu^2->half, 2=add residual->float
template<int EPI, int BT>
__global__ void __launch_bounds__(512, 1)
f16_gemm_kernel(const __half* __restrict__ A, const float* __restrict__ B,
                void* __restrict__ Cv, const float* __restrict__ addsrc,
                const float* __restrict__ alpha_ptr, int alpha_idx,
                int N, int K)
{
    extern __shared__ char smc[];
    const int tid = threadIdx.x;
    const int wid = tid >> 5, lane = tid & 31;
    const int g = lane >> 2, tig = lane & 3;
    const int wm = (wid & 3) * 64, wn = (wid >> 2) * 32;
    const int bn = blockIdx.x, bm = blockIdx.y;
    const int nk = K / GBK;
    const uint32_t sb = smem_u32(smc);

    const __half* Agm = A + (size_t)bm * GBM * K;
    const float*  Bgm = BT ? (B + (size_t)bn * GBN * K) : B;

    auto load_A = [&](int stage, int ktile) {
        uint32_t sa = sb + stage * A_STAGE_B;
        int kt = ktile * GBK;
        #pragma unroll
        for (int i = 0; i < 4; i++) {
            int c = tid + i * 512;
            int row = c >> 3, ch = c & 7;
            cp_async16(sa + (uint32_t)row * 144 + ch * 16,
                       Agm + (size_t)row * K + kt + ch * 8);
        }
    };

    float4 breg[2][2];
    auto ldg_B = [&](int ktile) {
        int kt = ktile * GBK;
        #pragma unroll
        for (int i = 0; i < 2; i++) {
            int c = tid + i * 512;
            const float* p;
            if (BT) {
                int row = c >> 3, ch = c & 7;
                p = Bgm + (size_t)row * K + kt + ch * 8;
            } else {
                int row = c >> 4, ch = c & 15;
                p = Bgm + (size_t)(kt + row) * N + bn * GBN + ch * 8;
            }
            breg[i][0] = *(const float4*)p;
            breg[i][1] = *(const float4*)(p + 4);
        }
    };
    auto sts_B = [&](int bstage) {
        #pragma unroll
        for (int i = 0; i < 2; i++) {
            int c = tid + i * 512;
            uint32_t off;
            if (BT) { int row = c >> 3, ch = c & 7;  off = (uint32_t)row * 144 + ch * 16; }
            else    { int row = c >> 4, ch = c & 15; off = (uint32_t)row * BROWB + ch * 16; }
            uint4 o;
            o.x = pack2h(breg[i][0].x, breg[i][0].y);
            o.y = pack2h(breg[i][0].z, breg[i][0].w);
            o.z = pack2h(breg[i][1].x, breg[i][1].y);
            o.w = pack2h(breg[i][1].z, breg[i][1].w);
            *(uint4*)&smc[B_BASE + bstage * B_STAGE_B + off] = o;
        }
    };

    uint32_t aoff[4], boff[2];
    #pragma unroll
    for (int mt = 0; mt < 4; mt++)
        aoff[mt] = (uint32_t)(wm + mt * 16 + (lane & 7) + ((lane >> 3) & 1) * 8) * 144
                 + ((lane >> 4) & 1) * 16;
    if (BT) {
        #pragma unroll
        for (int nb = 0; nb < 2; nb++)
            boff[nb] = (uint32_t)(wn + nb * 16 + (lane & 7) + ((lane >> 4) & 1) * 8) * 144
                     + ((lane >> 3) & 1) * 16;
    } else {
        #pragma unroll
        for (int nb = 0; nb < 2; nb++)
            boff[nb] = (uint32_t)((lane & 7) + ((lane >> 3) & 1) * 8) * BROWB
                     + (wn + nb * 16) * 2 + ((lane >> 4) & 1) * 16;
    }

    float acc[4][4][4];
    #pragma unroll
    for (int mt = 0; mt < 4; mt++)
        #pragma unroll
        for (int nt = 0; nt < 4; nt++)
            #pragma unroll
            for (int q = 0; q < 4; q++) acc[mt][nt][q] = 0.f;

    ldg_B(0); sts_B(0);
    ldg_B(1);
    #pragma unroll
    for (int s = 0; s < GSTAGES - 1; s++) { load_A(s, s); cp_async_commit(); }

    for (int k = 0; k < nk; k++) {
        cp_async_wait<GSTAGES - 2>();
        __syncthreads();
        if (k + 1 < nk) sts_B((k + 1) & 1);
        if (k + 2 < nk) ldg_B(k + 2);
        if (k + GSTAGES - 1 < nk) load_A((k + GSTAGES - 1) & (GSTAGES - 1),
                                         k + GSTAGES - 1);
        cp_async_commit();

        uint32_t sa = sb + (k & (GSTAGES - 1)) * A_STAGE_B;
        uint32_t sB = sb + B_BASE + (k & 1) * B_STAGE_B;

        #pragma unroll
        for (int ks = 0; ks < 4; ks++) {
            uint32_t a[4][4];
            #pragma unroll
            for (int mt = 0; mt < 4; mt++)
                ldsm_x4(a[mt][0], a[mt][1], a[mt][2], a[mt][3],
                        sa + aoff[mt] + ks * 32);
            #pragma unroll
            for (int nb = 0; nb < 2; nb++) {
                uint32_t b0, b1, b2, b3;
                if (BT) ldsm_x4(b0, b1, b2, b3, sB + boff[nb] + ks * 32);
                else    ldsm_x4_t(b0, b1, b2, b3, sB + boff[nb] + ks * 16 * BROWB);
                #pragma unroll
                for (int mt = 0; mt < 4; mt++) {
                    mma_f16(acc[mt][2 * nb][0], acc[mt][2 * nb][1],
                            acc[mt][2 * nb][2], acc[mt][2 * nb][3],
                            a[mt][0], a[mt][1], a[mt][2], a[mt][3], b0, b1);
                    mma_f16(acc[mt][2 * nb + 1][0], acc[mt][2 * nb + 1][1],
                            acc[mt][2 * nb + 1][2], acc[mt][2 * nb + 1][3],
                            a[mt][0], a[mt][1], a[mt][2], a[mt][3], b2, b3);
                }
            }
        }
    }

    float alpha = alpha_ptr ? alpha_ptr[alpha_idx] : 1.0f;
    #pragma unroll
    for (int mt = 0; mt < 4; mt++) {
        #pragma unroll
        for (int half_i = 0; half_i < 2; half_i++) {
            int row = bm * GBM + wm + mt * 16 + g + half_i * 8;
            #pragma unroll
            for (int nt = 0; nt < 4; nt++) {
                int col = bn * GBN + wn + nt * 8 + tig * 2;
                float vx = acc[mt][nt][half_i * 2 + 0] * alpha;
                float vy = acc[mt][nt][half_i * 2 + 1] * alpha;
                size_t idx = (size_t)row * N + col;
                if (EPI == 1) {
                    vx = fmaxf(vx, 0.f); vx = vx * vx;
                    vy = fmaxf(vy, 0.f); vy = vy * vy;
                    *(__half2*)((__half*)Cv + idx) = __floats2half2_rn(vx, vy);
                } else if (EPI == 2) {
                    float2 a2 = *(const float2*)&addsrc[idx];
                    float2 v; v.x = vx + a2.x; v.y = vy + a2.y;
                    *(float2*)((float*)Cv + idx) = v;
                } else {
                    float2 v; v.x = vx; v.y = vy;
                    *(float2*)((float*)Cv + idx) = v;
                }
            }
        }
    }
}

// ---------------- RMSNorm (fp16 output) ----------------
__global__ void __launch_bounds__(256) rmsnorm_kernel(const float* __restrict__ in,
                                                      __half* __restrict__ outp) {
    int t = blockIdx.x;
    const float* r = in + (size_t)t * DIM;
    float ss = 0.f;
    float vals[8];
    #pragma unroll
    for (int j = 0; j < 8; j++) {
        float v = r[threadIdx.x + j * 256];
        vals[j] = v; ss += v * v;
    }
    __shared__ float sred[8];
    for (int o = 16; o; o >>= 1) ss += __shfl_xor_sync(0xffffffffu, ss, o);
    if ((threadIdx.x & 31) == 0) sred[threadIdx.x >> 5] = ss;
    __syncthreads();
    float tot = 0.f;
    #pragma unroll
    for (int i = 0; i < 8; i++) tot += sred[i];
    float scale = rsqrtf(tot / (float)DIM + EPS_F);
    #pragma unroll
    for (int j = 0; j < 8; j++)
        outp[(size_t)t * DIM + threadIdx.x + j * 256] = __float2half_rn(vals[j] * scale);
}

// ---------------- gates v2: tiled, low weight traffic ----------------
__global__ void __launch_bounds__(256) gates2_kernel(
    const __half* __restrict__ xn, const float* __restrict__ agw,
    const float* __restrict__ vgw, float* __restrict__ agate,
    float* __restrict__ vgate)
{
    __shared__ __half xs[16][520];
    int t0 = blockIdx.x * 16;
    int t = threadIdx.x & 15, og = threadIdx.x >> 4;
    float acc0 = 0.f, acc1 = 0.f;
    for (int kc = 0; kc < 4; kc++) {
        #pragma unroll
        for (int i = 0; i < 4; i++) {
            int c = threadIdx.x + i * 256;
            int r = c >> 6, co = c & 63;
            *(uint4*)&xs[r][co * 8] =
                *(const uint4*)&xn[(size_t)(t0 + r) * DIM + kc * 512 + co * 8];
        }
        __syncthreads();
        const float* wa = agw + (size_t)og * DIM + kc * 512;
        const float* wv = vgw + (size_t)og * DIM + kc * 512;
        #pragma unroll 8
        for (int kk = 0; kk < 512; kk++) {
            float xv = __half2float(xs[t][kk]);
            acc0 = fmaf(xv, wa[kk], acc0);
            acc1 = fmaf(xv, wv[kk], acc1);
        }
        __syncthreads();
    }
    agate[(t0 + t) * NH + og] = 1.f / (1.f + expf(-acc0));
    vgate[(t0 + t) * NH + og] = 1.f / (1.f + expf(-acc1));
}

// ---------------- fused QKV post-processing: one warp per TWO adjacent rows ----------------
// pair p = hs/2 in [0,24): p<8 -> q rows, 8<=p<16 -> k rows (scatter shift), p>=16 -> v rows.
__global__ void __launch_bounds__(256) qkvpost_kernel(
    const float* __restrict__ qkv, __half* __restrict__ qh,
    __half* __restrict__ kh, __half* __restrict__ vh,
    const float* __restrict__ ve, const float* __restrict__ vgate,
    const float* __restrict__ cosb, const float* __restrict__ sinb,
    const int* __restrict__ key_offset)
{
    int gw = blockIdx.x * 8 + (threadIdx.x >> 5);
    int lane = threadIdx.x & 31;
    int p = gw % 24;
    int t = gw / 24;
    int hs0 = p * 2, hs1 = hs0 + 1;
    int d0 = lane * 4;

    float4 v0 = *(const float4*)&qkv[((size_t)t * 48 + hs0) * HD + d0];
    float4 v1 = *(const float4*)&qkv[((size_t)t * 48 + hs1) * HD + d0];

    if (p >= 16) {
        // ---- v update (2 heads) ----
        int h0 = hs0 - 32, h1 = hs1 - 32;
        float4 e0 = *(const float4*)&ve[((size_t)t * NH + h0) * HD + d0];
        float4 e1 = *(const float4*)&ve[((size_t)t * NH + h1) * HD + d0];
        float gv0 = vgate[t * NH + h0], gv1 = vgate[t * NH + h1];
        uint2 w0, w1;
        w0.x = pack2h(v0.x + gv0 * e0.x, v0.y + gv0 * e0.y);
        w0.y = pack2h(v0.z + gv0 * e0.z, v0.w + gv0 * e0.w);
        w1.x = pack2h(v1.x + gv1 * e1.x, v1.y + gv1 * e1.y);
        w1.y = pack2h(v1.z + gv1 * e1.z, v1.w + gv1 * e1.w);
        *(uint2*)&vh[((size_t)t * NH + h0) * HD + d0] = w0;
        *(uint2*)&vh[((size_t)t * NH + h1) * HD + d0] = w1;
        return;
    }

    // ---- q/k rmsnorm + rotary, two rows interleaved ----
    float ss0 = v0.x * v0.x + v0.y * v0.y + v0.z * v0.z + v0.w * v0.w;
    float ss1 = v1.x * v1.x + v1.y * v1.y + v1.z * v1.z + v1.w * v1.w;
    #pragma unroll
    for (int o = 16; o; o >>= 1) {
        ss0 += __shfl_xor_sync(0xffffffffu, ss0, o);
        ss1 += __shfl_xor_sync(0xffffffffu, ss1, o);
    }
    float sc0 = rsqrtf(ss0 / (float)HD + EPS_F);
    float sc1 = rsqrtf(ss1 / (float)HD + EPS_F);
    v0.x *= sc0; v0.y *= sc0; v0.z *= sc0; v0.w *= sc0;
    v1.x *= sc1; v1.y *= sc1; v1.z *= sc1; v1.w *= sc1;

    float p0x = __shfl_xor_sync(0xffffffffu, v0.x, 16);
    float p0y = __shfl_xor_sync(0xffffffffu, v0.y, 16);
    float p0z = __shfl_xor_sync(0xffffffffu, v0.z, 16);
    float p0w = __shfl_xor_sync(0xffffffffu, v0.w, 16);
    float p1x = __shfl_xor_sync(0xffffffffu, v1.x, 16);
    float p1y = __shfl_xor_sync(0xffffffffu, v1.y, 16);
    float p1z = __shfl_xor_sync(0xffffffffu, v1.z, 16);
    float p1w = __shfl_xor_sync(0xffffffffu, v1.w, 16);

    int ci = t * 64 + (d0 & 63);
    float4 c = *(const float4*)&cosb[ci];
    float4 s = *(const float4*)&sinb[ci];
    float4 o0, o1;
    if (lane < 16) {
        o0.x = v0.x * c.x + p0x * s.x;  o1.x = v1.x * c.x + p1x * s.x;
        o0.y = v0.y * c.y + p0y * s.y;  o1.y = v1.y * c.y + p1y * s.y;
        o0.z = v0.z * c.z + p0z * s.z;  o1.z = v1.z * c.z + p1z * s.z;
        o0.w = v0.w * c.w + p0w * s.w;  o1.w = v1.w * c.w + p1w * s.w;
    } else {
        o0.x = -p0x * s.x + v0.x * c.x; o1.x = -p1x * s.x + v1.x * c.x;
        o0.y = -p0y * s.y + v0.y * c.y; o1.y = -p1y * s.y + v1.y * c.y;
        o0.z = -p0z * s.z + v0.z * c.z; o1.z = -p1z * s.z + v1.z * c.z;
        o0.w = -p0w * s.w + v0.w * c.w; o1.w = -p1w * s.w + v1.w * c.w;
    }
    uint2 w0, w1;
    w0.x = pack2h(o0.x, o0.y); w0.y = pack2h(o0.z, o0.w);
    w1.x = pack2h(o1.x, o1.y); w1.y = pack2h(o1.z, o1.w);

    if (p < 8) {
        *(uint2*)&qh[((size_t)t * NH + hs0) * HD + d0] = w0;
        *(uint2*)&qh[((size_t)t * NH + hs1) * HD + d0] = w1;
    } else {
        int h0 = hs0 - 16, h1 = hs1 - 16;
        int ko = key_offset[0];
        bool up = ((d0 >> 5) & 1) != 0;   // quarters 1 and 3
        if (!ko || !up) {
            *(uint2*)&kh[((size_t)t * NH + h0) * HD + d0] = w0;
            *(uint2*)&kh[((size_t)t * NH + h1) * HD + d0] = w1;
        } else {
            if (t + 1 < T_SEQ) {
                *(uint2*)&kh[((size_t)(t + 1) * NH + h0) * HD + d0] = w0;
                *(uint2*)&kh[((size_t)(t + 1) * NH + h1) * HD + d0] = w1;
            }
            if (t == 0) {
                *(uint2*)&kh[((size_t)0 * NH + h0) * HD + d0] = w0;
                *(uint2*)&kh[((size_t)0 * NH + h1) * HD + d0] = w1;
            }
        }
    }
}

// ================= fp16 MMA flash attention =================
#define FROW 136
#define FL_SMEM (3 * 64 * FROW * 2 + 256)

__global__ void __launch_bounds__(128) flash_mma_kernel(
    const __half* __restrict__ qh, const __half* __restrict__ kh,
    const __half* __restrict__ vh, const int* __restrict__ docs,
    const float* __restrict__ attn_scale, const float* __restrict__ agate,
    __half* __restrict__ y)
{
    extern __shared__ __half fh[];
    __half* Qs = fh;
    __half* Ks = fh + 64 * FROW;
    __half* Vs = fh + 2 * 64 * FROW;
    int*    kd = (int*)(fh + 3 * 64 * FROW);

    const int tid = threadIdx.x, wid = tid >> 5, lane = tid & 31;
    const int g = lane >> 2, tig = lane & 3;
    const int h = blockIdx.y;
    const int qi = (int)gridDim.x - 1 - (int)blockIdx.x;
    const int qbase = qi * 64;
    const float scale = attn_scale[0];

    #pragma unroll
    for (int i = 0; i < 8; i++) {
        int c = tid + i * 128;
        int r = c >> 4, co = c & 15;
        *(uint4*)&Qs[r * FROW + co * 8] =
            *(const uint4*)&qh[((size_t)(qbase + r) * NH + h) * HD + co * 8];
    }
    const int rg0 = qbase + wid * 16 + g;
    const int rg1 = rg0 + 8;
    const int qd0 = docs[rg0], qd1 = docs[rg1];
    const int qdmin = docs[qbase];

    const uint32_t sQ = smem_u32(Qs), sK = smem_u32(Ks), sV = smem_u32(Vs);
    const uint32_t qoff = (uint32_t)(wid * 16 + (lane & 7) + ((lane >> 3) & 1) * 8) * (FROW * 2)
                        + ((lane >> 4) & 1) * 16;
    uint32_t koff[4], voff[8];
    #pragma unroll
    for (int nb = 0; nb < 4; nb++)
        koff[nb] = (uint32_t)(nb * 16 + (lane & 7) + ((lane >> 4) & 1) * 8) * (FROW * 2)
                 + ((lane >> 3) & 1) * 16;
    #pragma unroll
    for (int nb = 0; nb < 8; nb++)
        voff[nb] = (uint32_t)((lane & 7) + ((lane >> 3) & 1) * 8) * (FROW * 2)
                 + nb * 32 + ((lane >> 4) & 1) * 16;

    float o[16][4] = {};
    float m0 = NEG_INF_F, m1 = NEG_INF_F, l0 = 0.f, l1 = 0.f;
    __syncthreads();

    for (int kb = 0; kb <= qi; kb++) {
        const int kbase = kb * 64;
        if (docs[kbase + 63] < qdmin) continue;
        __syncthreads();
        #pragma unroll
        for (int i = 0; i < 8; i++) {
            int c = tid + i * 128;
            int r = c >> 4, co = c & 15;
            *(uint4*)&Ks[r * FROW + co * 8] =
                *(const uint4*)&kh[((size_t)(kbase + r) * NH + h) * HD + co * 8];
            *(uint4*)&Vs[r * FROW + co * 8] =
                *(const uint4*)&vh[((size_t)(kbase + r) * NH + h) * HD + co * 8];
        }
        if (tid < 64) kd[tid] = docs[kbase + tid];
        __syncthreads();

        float s[8][4] = {};
        #pragma unroll
        for (int ks = 0; ks < 8; ks++) {
            uint32_t a0, a1, a2, a3;
            ldsm_x4(a0, a1, a2, a3, sQ + qoff + ks * 32);
            #pragma unroll
            for (int nb = 0; nb < 4; nb++) {
                uint32_t b0, b1, b2, b3;
                ldsm_x4(b0, b1, b2, b3, sK + koff[nb] + ks * 32);
                mma_f16(s[2 * nb][0], s[2 * nb][1], s[2 * nb][2], s[2 * nb][3],
                        a0, a1, a2, a3, b0, b1);
                mma_f16(s[2 * nb + 1][0], s[2 * nb + 1][1], s[2 * nb + 1][2], s[2 * nb + 1][3],
                        a0, a1, a2, a3, b2, b3);
            }
        }

        float mx0 = m0, mx1 = m1;
        #pragma unroll
        for (int nt = 0; nt < 8; nt++) {
            int c0i = kbase + nt * 8 + 2 * tig;
            int d0 = kd[nt * 8 + 2 * tig], d1 = kd[nt * 8 + 2 * tig + 1];
            float v00 = (c0i     <= rg0 && d0 == qd0) ? s[nt][0] * scale : NEG_INF_F;
            float v01 = (c0i + 1 <= rg0 && d1 == qd0) ? s[nt][1] * scale : NEG_INF_F;
            float v10 = (c0i     <= rg1 && d0 == qd1) ? s[nt][2] * scale : NEG_INF_F;
            float v11 = (c0i + 1 <= rg1 && d1 == qd1) ? s[nt][3] * scale : NEG_INF_F;
            s[nt][0] = v00; s[nt][1] = v01; s[nt][2] = v10; s[nt][3] = v11;
            mx0 = fmaxf(mx0, fmaxf(v00, v01));
            mx1 = fmaxf(mx1, fmaxf(v10, v11));
        }
        mx0 = fmaxf(mx0, __shfl_xor_sync(0xffffffffu, mx0, 1));
        mx0 = fmaxf(mx0, __shfl_xor_sync(0xffffffffu, mx0, 2));
        mx1 = fmaxf(mx1, __shfl_xor_sync(0xffffffffu, mx1, 1));
        mx1 = fmaxf(mx1, __shfl_xor_sync(0xffffffffu, mx1, 2));
        float al0 = __expf(m0 - mx0), al1 = __expf(m1 - mx1);
        m0 = mx0; m1 = mx1;

        float sum0 = 0.f, sum1 = 0.f;
        #pragma unroll
        for (int nt = 0; nt < 8; nt++) {
            s[nt][0] = __expf(s[nt][0] - m0);
            s[nt][1] = __expf(s[nt][1] - m0);
            s[nt][2] = __expf(s[nt][2] - m1);
            s[nt][3] = __expf(s[nt][3] - m1);
            sum0 += s[nt][0] + s[nt][1];
            sum1 += s[nt][2] + s[nt][3];
        }
        sum0 += __shfl_xor_sync(0xffffffffu, sum0, 1);
        sum0 += __shfl_xor_sync(0xffffffffu, sum0, 2);
        sum1 += __shfl_xor_sync(0xffffffffu, sum1, 1);
        sum1 += __shfl_xor_sync(0xffffffffu, sum1, 2);
        l0 = l0 * al0 + sum0;
        l1 = l1 * al1 + sum1;
        #pragma unroll
        for (int nt = 0; nt < 16; nt++) {
            o[nt][0] *= al0; o[nt][1] *= al0;
            o[nt][2] *= al1; o[nt][3] *= al1;
        }

        uint32_t pa[4][4];
        #pragma unroll
        for (int kc = 0; kc < 4; kc++) {
            pa[kc][0] = pack2h(s[2 * kc][0], s[2 * kc][1]);
            pa[kc][1] = pack2h(s[2 * kc][2], s[2 * kc][3]);
            pa[kc][2] = pack2h(s[2 * kc + 1][0], s[2 * kc + 1][1]);
            pa[kc][3] = pack2h(s[2 * kc + 1][2], s[2 * kc + 1][3]);
        }
        #pragma unroll
        for (int kc = 0; kc < 4; kc++) {
            #pragma unroll
            for (int nb = 0; nb < 8; nb++) {
                uint32_t b0, b1, b2, b3;
                ldsm_x4_t(b0, b1, b2, b3, sV + voff[nb] + kc * 16 * (FROW * 2));
                mma_f16(o[2 * nb][0], o[2 * nb][1], o[2 * nb][2], o[2 * nb][3],
                        pa[kc][0], pa[kc][1], pa[kc][2], pa[kc][3], b0, b1);
                mma_f16(o[2 * nb + 1][0], o[2 * nb + 1][1], o[2 * nb + 1][2], o[2 * nb + 1][3],
                        pa[kc][0], pa[kc][1], pa[kc][2], pa[kc][3], b2, b3);
            }
        }
    }

    float f0 = (1.f / l0) * agate[rg0 * NH + h];
    float f1 = (1.f / l1) * agate[rg1 * NH + h];
    #pragma unroll
    for (int nt = 0; nt < 16; nt++) {
        *(__half2*)&y[(size_t)rg0 * DIM + h * HD + nt * 8 + 2 * tig] =
            __floats2half2_rn(o[nt][0] * f0, o[nt][1] * f0);
        *(__half2*)&y[(size_t)rg1 * DIM + h * HD + nt * 8 + 2 * tig] =
            __floats2half2_rn(o[nt][2] * f1, o[nt][3] * f1);
    }
}

// ---------------- launch ----------------
extern "C" void kernel_launch(void* const* d_in, const int* in_sizes, int n_in,
                              void* d_out, int out_size) {
    const float* x           = (const float*)d_in[0];
    const float* ve          = (const float*)d_in[1];
    const float* qkvo_w      = (const float*)d_in[2];
    const float* attn_gate_w = (const float*)d_in[3];
    const float* ve_gate_w   = (const float*)d_in[4];
    const float* c_fc        = (const float*)d_in[5];
    const float* c_proj      = (const float*)d_in[6];
    const float* sa_lambdas  = (const float*)d_in[7];
    const float* cosb        = (const float*)d_in[8];
    const float* sinb        = (const float*)d_in[9];
    const float* attn_scale  = (const float*)d_in[10];
    const int*   docs        = (const int*)d_in[11];
    const int*   key_offset  = (const int*)d_in[12];
    float*       out         = (float*)d_out;

    __half *xn, *qhp, *khp, *vhp, *y, *hbuf;
    float *qkv, *x1, *agate, *vgate;
    cudaGetSymbolAddress((void**)&xn,    g_xn);
    cudaGetSymbolAddress((void**)&qkv,   g_qkv);
    cudaGetSymbolAddress((void**)&qhp,   g_qh);
    cudaGetSymbolAddress((void**)&khp,   g_kh);
    cudaGetSymbolAddress((void**)&vhp,   g_vh);
    cudaGetSymbolAddress((void**)&y,     g_y);
    cudaGetSymbolAddress((void**)&x1,    g_x1);
    cudaGetSymbolAddress((void**)&hbuf,  g_h);
    cudaGetSymbolAddress((void**)&agate, g_agate);
    cudaGetSymbolAddress((void**)&vgate, g_vgate);

    cudaFuncSetAttribute(flash_mma_kernel, cudaFuncAttributeMaxDynamicSharedMemorySize,
                         FL_SMEM);
    cudaFuncSetAttribute((const void*)f16_gemm_kernel<0,1>,
                         cudaFuncAttributeMaxDynamicSharedMemorySize, GEMM_SMEM);
    cudaFuncSetAttribute((const void*)f16_gemm_kernel<1,1>,
                         cudaFuncAttributeMaxDynamicSharedMemorySize, GEMM_SMEM);
    cudaFuncSetAttribute((const void*)f16_gemm_kernel<2,1>,
                         cudaFuncAttributeMaxDynamicSharedMemorySize, GEMM_SMEM);
    cudaFuncSetAttribute((const void*)f16_gemm_kernel<2,0>,
                         cudaFuncAttributeMaxDynamicSharedMemorySize, GEMM_SMEM);

    // 1. xn = fp16(rmsnorm(x))
    rmsnorm_kernel<<<T_SEQ, 256>>>(x, xn);
    // 2. gate logits
    gates2_kernel<<<T_SEQ / 16, 256>>>(xn, attn_gate_w, ve_gate_w, agate, vgate);
    // 3. qkv = lam0 * xn @ Wqkv^T  (fp32 out; B fp32 converted in-kernel)
    f16_gemm_kernel<0,1><<<dim3(3 * DIM / GBN, T_SEQ / GBM), 512, GEMM_SMEM>>>(
        xn, qkvo_w, qkv, nullptr, sa_lambdas, 0, 3 * DIM, DIM);
    // 4. fused QKV post (2 rows per warp; q/k rmsnorm+rotary with scatter shift, v update)
    qkvpost_kernel<<<(T_SEQ * 24) / 8, 256>>>(
        qkv, qhp, khp, vhp, ve, vgate, cosb, sinb, key_offset);
    // 5. fp16 MMA flash attention -> y (fp16)
    flash_mma_kernel<<<dim3(T_SEQ / 64, NH), 128, FL_SMEM>>>(
        qhp, khp, vhp, docs, attn_scale, agate, y);
    // 6. x1 = x + lam1 * y @ Wo^T
    f16_gemm_kernel<2,1><<<dim3(DIM / GBN, T_SEQ / GBM), 512, GEMM_SMEM>>>(
        y, qkvo_w + (size_t)3 * DIM * DIM, x1, x, sa_lambdas, 1, DIM, DIM);
    // 7. xn = fp16(rmsnorm(x1))
    rmsnorm_kernel<<<T_SEQ, 256>>>(x1, xn);
    // 8. h = fp16(relu(xn @ c_fc^T)^2)
    f16_gemm_kernel<1,1><<<dim3(FFN / GBN, T_SEQ / GBM), 512, GEMM_SMEM>>>(
        xn, c_fc, hbuf, nullptr, nullptr, 0, FFN, DIM);
    // 9. out = x1 + h @ c_proj  (B native [K,N] fp32, trans-ldmatrix path)
    f16_gemm_kernel<2,0><<<dim3(DIM / GBN, T_SEQ / GBM), 512, GEMM_SMEM>>>(
        hbuf, c_proj, out, x1, nullptr, 0, DIM, FFN);
}